// round 1
// baseline (speedup 1.0000x reference)
#include <cuda_runtime.h>
#include <math.h>

// Problem constants (fixed by the dataset)
#define LL   4
#define BB   16
#define NN   4096
#define DD   1024
#define KK   20
#define KSEL 100
#define LD   (LL * DD)      // 4096, concatenated feature dim
#define NCH  8              // split-K chunks for Gram
#define KC   (LD / NCH)     // 512

// ---------------- scratch (static device globals; no allocation) ----------
__device__ int   g_topidx[BB * KSEL];
__device__ float g_X[(size_t)BB * KSEL * LD];                 // 26.2 MB gathered+stacked tokens
__device__ float g_A[(size_t)BB * KSEL * DD];                 // 6.5 MB layer-averaged tokens
__device__ float g_Gpart[(size_t)BB * NCH * KSEL * KSEL];     // 5.1 MB split-K partials
__device__ float g_G[(size_t)BB * KSEL * KSEL];               // 640 KB Gram
__device__ int   g_labels[BB * KSEL];

// kmeans init indices = jnp.linspace(0, 99, 20).astype(int32)
__constant__ int c_init[KK] = {0, 5, 10, 15, 20, 26, 31, 36, 41, 46,
                               52, 57, 62, 67, 72, 78, 83, 88, 93, 99};

// ---------------- K1: score + per-batch bitonic top-100 -------------------
// score ordering == ordering of sum_l (a1 - a0); softmax is strictly monotone.
// key = (ordered_float(score) << 32) | (0xFFFFFFFF - n)  -> descending sort,
// ties broken toward lower index, matching lax.top_k. We sort ~key ascending.
__global__ void score_sort_kernel(const float* __restrict__ am) {
    __shared__ unsigned long long keys[NN];
    const int b   = blockIdx.x;
    const int tid = threadIdx.x;

    for (int n = tid; n < NN; n += 1024) {
        float s = 0.f;
#pragma unroll
        for (int l = 0; l < LL; l++) {
            const float* p = am + ((size_t)((l * BB + b) * NN + n)) * 2;
            s += p[1] - p[0];
        }
        unsigned u = __float_as_uint(s);
        u = (u & 0x80000000u) ? ~u : (u | 0x80000000u);  // order-preserving map
        unsigned long long key =
            ((unsigned long long)u << 32) |
            (unsigned long long)(0xFFFFFFFFu - (unsigned)n);
        keys[n] = ~key;
    }
    __syncthreads();

    for (int k = 2; k <= NN; k <<= 1) {
        for (int j = k >> 1; j > 0; j >>= 1) {
            for (int t = tid; t < NN / 2; t += 1024) {
                int i   = ((t & ~(j - 1)) << 1) | (t & (j - 1));
                int ixj = i | j;
                unsigned long long a = keys[i], c = keys[ixj];
                bool up = ((i & k) == 0);
                if ((a > c) == up) { keys[i] = c; keys[ixj] = a; }
            }
            __syncthreads();
        }
    }

    if (tid < KSEL) {
        unsigned long long key = ~keys[tid];
        g_topidx[b * KSEL + tid] =
            (int)(0xFFFFFFFFu - (unsigned)(key & 0xFFFFFFFFull));
    }
}

// ---------------- K2: gather selected tokens, build stacked X and avg A ---
__global__ void gather_kernel(const float* __restrict__ pt) {
    const int i = blockIdx.x;           // selected-token index 0..99
    const int b = blockIdx.y;
    const int tid = threadIdx.x;        // 256 threads, float4 over D=1024
    const int n = g_topidx[b * KSEL + i];
    const int d = tid * 4;

    float4 acc = make_float4(0.f, 0.f, 0.f, 0.f);
#pragma unroll
    for (int l = 0; l < LL; l++) {
        const float4 v = *(const float4*)(pt +
            (((size_t)(l * BB + b) * NN + n) * DD + d));
        *(float4*)(g_X + ((size_t)(b * KSEL + i)) * LD + l * DD + d) = v;
        acc.x += v.x; acc.y += v.y; acc.z += v.z; acc.w += v.w;
    }
    acc.x *= 0.25f; acc.y *= 0.25f; acc.z *= 0.25f; acc.w *= 0.25f;
    *(float4*)(g_A + ((size_t)(b * KSEL + i)) * DD + d) = acc;
}

// ---------------- K3: Gram G = X X^T, split-K partials --------------------
// grid (NCH, BB), 256 threads (16x16), 7x7 register tile covering 112x112.
__global__ void gram_kernel() {
    __shared__ float Xs[KSEL][33];
    const int ch = blockIdx.x, b = blockIdx.y;
    const int tx = threadIdx.x & 15;
    const int ty = threadIdx.x >> 4;

    float acc[7][7];
#pragma unroll
    for (int r = 0; r < 7; r++)
#pragma unroll
        for (int c = 0; c < 7; c++) acc[r][c] = 0.f;

    const float* Xb = g_X + (size_t)b * KSEL * LD;
    const int kbeg = ch * KC;

    for (int k0 = 0; k0 < KC; k0 += 32) {
        for (int e = threadIdx.x; e < KSEL * 32; e += 256) {
            int r = e >> 5, c = e & 31;
            Xs[r][c] = Xb[(size_t)r * LD + kbeg + k0 + c];
        }
        __syncthreads();

        for (int kk = 0; kk < 32; kk++) {
            float a[7], bv[7];
#pragma unroll
            for (int r = 0; r < 7; r++) {
                int R = ty + 16 * r;
                a[r] = (R < KSEL) ? Xs[R][kk] : 0.f;
            }
#pragma unroll
            for (int c = 0; c < 7; c++) {
                int C = tx + 16 * c;
                bv[c] = (C < KSEL) ? Xs[C][kk] : 0.f;
            }
#pragma unroll
            for (int r = 0; r < 7; r++)
#pragma unroll
                for (int c = 0; c < 7; c++)
                    acc[r][c] = fmaf(a[r], bv[c], acc[r][c]);
        }
        __syncthreads();
    }

    float* Gp = g_Gpart + ((size_t)b * NCH + ch) * (KSEL * KSEL);
#pragma unroll
    for (int r = 0; r < 7; r++) {
        int R = ty + 16 * r;
#pragma unroll
        for (int c = 0; c < 7; c++) {
            int C = tx + 16 * c;
            if (R < KSEL && C < KSEL) Gp[R * KSEL + C] = acc[r][c];
        }
    }
}

// ---------------- K4: deterministic split-K reduction ---------------------
__global__ void reduce_kernel() {
    int e = blockIdx.x * blockDim.x + threadIdx.x;
    if (e >= BB * KSEL * KSEL) return;
    int b = e / (KSEL * KSEL);
    int r = e - b * (KSEL * KSEL);
    float s = 0.f;
#pragma unroll
    for (int ch = 0; ch < NCH; ch++)
        s += g_Gpart[((size_t)b * NCH + ch) * (KSEL * KSEL) + r];
    g_G[e] = s;
}

// ---------------- K5: Lloyd kmeans in Gram space --------------------------
// M[j][i] = x_i . c_j ; q[j] = |c_j|^2 ; both maintained persistently so
// empty clusters keep their old centroid (matches jnp.where(cnt>0,...,c)).
// 10 update rounds + final assign = 11 assigns total, matching the scan.
__global__ void kmeans_kernel() {
    __shared__ float Gs[KSEL * KSEL];   // 40000 B
    __shared__ float M[KK * KSEL];      //  8000 B
    __shared__ float q[KK];
    __shared__ int   labels[KSEL];
    __shared__ int   cnt[KK];
    __shared__ float invc[KK];
    const int b = blockIdx.x, tid = threadIdx.x;   // 128 threads

    for (int e = tid; e < KSEL * KSEL; e += 128)
        Gs[e] = g_G[(size_t)b * KSEL * KSEL + e];
    __syncthreads();

    if (tid < KK) {
        int p = c_init[tid];
        q[tid] = Gs[p * KSEL + p];
    }
    for (int e = tid; e < KK * KSEL; e += 128) {
        int j = e / KSEL, i = e - j * KSEL;
        M[e] = Gs[c_init[j] * KSEL + i];
    }
    __syncthreads();

    for (int t = 0; t <= 10; t++) {
        // --- assign: argmin_j (Gii - 2 M[j,i] + q[j]), first-min wins ---
        if (tid < KSEL) {
            float gii  = Gs[tid * KSEL + tid];
            float best = 3.4e38f;
            int   bj   = 0;
#pragma unroll
            for (int j = 0; j < KK; j++) {
                float d2 = gii - 2.f * M[j * KSEL + tid] + q[j];
                if (d2 < best) { best = d2; bj = j; }
            }
            labels[tid] = bj;
        }
        __syncthreads();
        if (t == 10) break;

        // --- counts ---
        if (tid < KK) cnt[tid] = 0;
        __syncthreads();
        if (tid < KSEL) atomicAdd(&cnt[labels[tid]], 1);
        __syncthreads();
        if (tid < KK) invc[tid] = (cnt[tid] > 0) ? 1.f / (float)cnt[tid] : 0.f;
        __syncthreads();

        // --- M update: column i gathers per-cluster sums in one pass ---
        if (tid < KSEL) {
            float acc[KK];
#pragma unroll
            for (int j = 0; j < KK; j++) acc[j] = 0.f;
            for (int p = 0; p < KSEL; p++)
                acc[labels[p]] += Gs[p * KSEL + tid];   // ascending p
#pragma unroll
            for (int j = 0; j < KK; j++)
                if (cnt[j] > 0) M[j * KSEL + tid] = acc[j] * invc[j];
        }
        __syncthreads();

        // --- q update (only for non-empty clusters) ---
        if (tid < KK && cnt[tid] > 0) {
            float acc = 0.f;
            for (int p = 0; p < KSEL; p++)
                if (labels[p] == tid) acc += M[tid * KSEL + p];
            q[tid] = acc * invc[tid];
        }
        __syncthreads();
    }

    if (tid < KSEL) g_labels[b * KSEL + tid] = labels[tid];
}

// ---------------- K6: cluster-mean-of-means + L2 normalize ----------------
__global__ void final_kernel(float* __restrict__ out) {
    __shared__ int   cnt[KK];
    __shared__ float coef[KSEL];
    __shared__ float red[256];
    const int b = blockIdx.x, tid = threadIdx.x;   // 256 threads

    if (tid < KK) cnt[tid] = 0;
    __syncthreads();
    if (tid < KSEL) atomicAdd(&cnt[g_labels[b * KSEL + tid]], 1);
    __syncthreads();
    if (tid < KSEL)
        coef[tid] = 1.f / (20.f * (float)cnt[g_labels[b * KSEL + tid]]);
    __syncthreads();

    const int d = tid * 4;
    float4 acc = make_float4(0.f, 0.f, 0.f, 0.f);
    for (int i = 0; i < KSEL; i++) {
        float c = coef[i];
        float4 v = *(const float4*)(g_A + ((size_t)(b * KSEL + i)) * DD + d);
        acc.x = fmaf(c, v.x, acc.x);
        acc.y = fmaf(c, v.y, acc.y);
        acc.z = fmaf(c, v.z, acc.z);
        acc.w = fmaf(c, v.w, acc.w);
    }

    red[tid] = acc.x * acc.x + acc.y * acc.y + acc.z * acc.z + acc.w * acc.w;
    __syncthreads();
    for (int s = 128; s > 0; s >>= 1) {
        if (tid < s) red[tid] += red[tid + s];
        __syncthreads();
    }
    float inv = 1.f / fmaxf(sqrtf(red[0]), 1e-12f);
    float4 o = make_float4(acc.x * inv, acc.y * inv, acc.z * inv, acc.w * inv);
    *(float4*)(out + (size_t)b * DD + d) = o;
}

// ---------------- launch ---------------------------------------------------
extern "C" void kernel_launch(void* const* d_in, const int* in_sizes, int n_in,
                              void* d_out, int out_size) {
    const float* pt = (const float*)d_in[0];   // patch_tokens [L,B,N,D] f32
    const float* am = (const float*)d_in[1];   // anomaly_maps [L,B,N,2] f32
    float* out = (float*)d_out;                // [B,D] f32

    score_sort_kernel<<<BB, 1024>>>(am);
    gather_kernel<<<dim3(KSEL, BB), 256>>>(pt);
    gram_kernel<<<dim3(NCH, BB), 256>>>();
    reduce_kernel<<<(BB * KSEL * KSEL + 255) / 256, 256>>>();
    kmeans_kernel<<<BB, 128>>>();
    final_kernel<<<BB, 256>>>(out);
}